// round 6
// baseline (speedup 1.0000x reference)
#include <cuda_runtime.h>
#include <math.h>

// Fast MDCT: B=8, T=2^20, F=2048, hop=1024, N=1024, n_frames=1025.
// fold 2048 real -> DCT-IV -> 512-pt complex FFT (3 radix-8 Stockham stages,
// stage 1 fused with fold, stage 3 fused with post-twiddle).
// All trig from per-CTA shared-memory tables (built with sincospif, exact args).

#define NBINS 1024
#define PHYS(i) ((i) + ((i) >> 4))     // float2 pad: +1 per 16
#define XP(i)   ((i) + ((i) >> 5))     // float  pad: +1 per 32
#define BUF_F2 544                      // 512 float2 padded
#define GROUP_F2 (2 * BUF_F2)           // bufA + bufB
#define NGROUPS 4
#define NTHREADS (64 * NGROUPS)
#define TBL_F2 (512 + 512 + 512 + 448 + 56)   // wpair, apre, post, tw1, tw2 = 2040
#define SMEM_F2 (TBL_F2 + NGROUPS * GROUP_F2)
#define SMEM_BYTES (SMEM_F2 * (int)sizeof(float2))

#define SCALE 0.04419417382415922f     // sqrt(2/1024)

__device__ __forceinline__ float2 cmulf(float2 a, float2 b) {
    return make_float2(a.x * b.x - a.y * b.y, a.x * b.y + a.y * b.x);
}
__device__ __forceinline__ float2 caddf(float2 a, float2 b) { return make_float2(a.x + b.x, a.y + b.y); }
__device__ __forceinline__ float2 csubf(float2 a, float2 b) { return make_float2(a.x - b.x, a.y - b.y); }

// In-register 8-pt DFT (DIF), natural-order output.
__device__ __forceinline__ void dft8(const float2 a[8], float2 A[8]) {
    float2 e0 = caddf(a[0], a[4]), o0 = csubf(a[0], a[4]);
    float2 e1 = caddf(a[1], a[5]), o1 = csubf(a[1], a[5]);
    float2 e2 = caddf(a[2], a[6]), o2 = csubf(a[2], a[6]);
    float2 e3 = caddf(a[3], a[7]), o3 = csubf(a[3], a[7]);

    const float C = 0.70710678118654752f;
    float2 p1 = make_float2(C * (o1.x + o1.y), C * (o1.y - o1.x));
    float2 p2 = make_float2(o2.y, -o2.x);
    float2 p3 = make_float2(C * (o3.y - o3.x), -C * (o3.x + o3.y));

    float2 t0 = caddf(e0, e2), t1 = csubf(e0, e2);
    float2 t2 = caddf(e1, e3), t3 = csubf(e1, e3);
    A[0] = caddf(t0, t2);
    A[4] = csubf(t0, t2);
    A[2] = make_float2(t1.x + t3.y, t1.y - t3.x);
    A[6] = make_float2(t1.x - t3.y, t1.y + t3.x);

    float2 s0 = caddf(o0, p2), s1 = csubf(o0, p2);
    float2 s2 = caddf(p1, p3), s3 = csubf(p1, p3);
    A[1] = caddf(s0, s2);
    A[5] = csubf(s0, s2);
    A[3] = make_float2(s1.x + s3.y, s1.y - s3.x);
    A[7] = make_float2(s1.x - s3.y, s1.y + s3.x);
}

// Fold + pre-twiddle + stage-1 radix-8.  EDGE=true adds bounds checks.
template <bool EDGE>
__device__ __forceinline__ void fold_stage1(
    const float* __restrict__ xf, int T_minus_start, int l,
    const float2* __restrict__ wpair, const float2* __restrict__ apre,
    const float2* __restrict__ tw1, float2* __restrict__ bufA)
{
    float2 v[8];
#pragma unroll
    for (int j = 0; j < 8; j++) {
        int n = l + 64 * j;
        int i0, i1, i2, i3;
        if (j < 4) { i0 = 1535 - 2 * n; i1 = 1536 + 2 * n; i2 = 511 - 2 * n;  i3 = 512 + 2 * n; }
        else       { i0 = 2 * n - 512;  i1 = 1535 - 2 * n; i2 = 512 + 2 * n;  i3 = 2559 - 2 * n; }

        float x0, x1, x2, x3;
        if (EDGE) {
            // valid iff 0 <= start+i < T  <=>  (unsigned)(i - (-start)) < T ... use offset form
            x0 = ((unsigned)(i0 + 0x40000000 - T_minus_start) < 0x40000000u) ? 0.f : 0.f; // placeholder (unused)
            x0 = x1 = x2 = x3 = 0.f;
            // direct guarded loads (start may be negative or frame may overrun T)
            // xf = xb + start; index i valid iff (start + i) in [0,T) <=> i in [-start, T-start)
            // We pass T_minus_start = T - start and use (i + start >= 0) via i < T-start && i >= -start.
        }
        if (EDGE) {
            int neg_start = T_minus_start - (1 << 30); // not used; see below
            (void)neg_start;
        }
        if (!EDGE) {
            x0 = xf[i0]; x1 = xf[i1]; x2 = xf[i2]; x3 = xf[i3];
        } else {
            // i valid iff i >= lo and i < hi, with lo = -(start), hi = T - start.
            // Encode: lo = T_minus_start - T_CONST is messy; instead recompute via globals below.
            extern __device__ int g_edge_lo_dummy; (void)g_edge_lo_dummy;
            x0 = x1 = x2 = x3 = 0.f;
        }

        float2 w = wpair[n];     // (wc, ws)
        float E, O;
        if (j < 4) { E = -(w.x * x0 + w.y * x1); O =  w.y * x2 - w.x * x3; }
        else       { E =   w.y * x0 - w.x * x1; O = -(w.x * x2 + w.y * x3); }
        float2 a = apre[n];
        v[j] = make_float2(E * a.x - O * a.y, E * a.y + O * a.x);
    }
    float2 A[8];
    dft8(v, A);
#pragma unroll
    for (int t = 1; t < 8; t++) A[t] = cmulf(A[t], tw1[(t - 1) * 64 + l]);
#pragma unroll
    for (int t = 0; t < 8; t++) bufA[PHYS(8 * l + t)] = A[t];
}

// Clean edge-capable version (used for both paths to avoid the messy template above
// being instantiated with broken guards): guards compiled out when EDGE==false.
template <bool EDGE>
__device__ __forceinline__ void fold_stage1_v2(
    const float* __restrict__ xb, int start, int T, int l,
    const float2* __restrict__ wpair, const float2* __restrict__ apre,
    const float2* __restrict__ tw1, float2* __restrict__ bufA)
{
    const float* xf = xb + start;
    float2 v[8];
#pragma unroll
    for (int j = 0; j < 8; j++) {
        int n = l + 64 * j;
        int i0, i1, i2, i3;
        if (j < 4) { i0 = 1535 - 2 * n; i1 = 1536 + 2 * n; i2 = 511 - 2 * n;  i3 = 512 + 2 * n; }
        else       { i0 = 2 * n - 512;  i1 = 1535 - 2 * n; i2 = 512 + 2 * n;  i3 = 2559 - 2 * n; }

        float x0, x1, x2, x3;
        if (EDGE) {
            int g0 = start + i0, g1 = start + i1, g2 = start + i2, g3 = start + i3;
            x0 = ((unsigned)g0 < (unsigned)T) ? xb[g0] : 0.f;
            x1 = ((unsigned)g1 < (unsigned)T) ? xb[g1] : 0.f;
            x2 = ((unsigned)g2 < (unsigned)T) ? xb[g2] : 0.f;
            x3 = ((unsigned)g3 < (unsigned)T) ? xb[g3] : 0.f;
        } else {
            x0 = xf[i0]; x1 = xf[i1]; x2 = xf[i2]; x3 = xf[i3];
        }

        float2 w = wpair[n];     // (wc, ws)
        float E, O;
        if (j < 4) { E = -(w.x * x0 + w.y * x1); O =  w.y * x2 - w.x * x3; }
        else       { E =   w.y * x0 - w.x * x1; O = -(w.x * x2 + w.y * x3); }
        float2 a = apre[n];
        v[j] = make_float2(E * a.x - O * a.y, E * a.y + O * a.x);
    }
    float2 A[8];
    dft8(v, A);
#pragma unroll
    for (int t = 1; t < 8; t++) A[t] = cmulf(A[t], tw1[(t - 1) * 64 + l]);
#pragma unroll
    for (int t = 0; t < 8; t++) bufA[PHYS(8 * l + t)] = A[t];
}

__global__ __launch_bounds__(NTHREADS, 4) void mdct_main(
    const float* __restrict__ x, float* __restrict__ out,
    int T, int n_frames)
{
    extern __shared__ float2 smem2[];
    float2* wpair = smem2;              // 512
    float2* apre  = wpair + 512;        // 512
    float2* postt = apre + 512;         // 512 (scale folded in)
    float2* tw1   = postt + 512;        // 448: [t-1][l] = exp(-i*pi*t*l/256)
    float2* tw2   = tw1 + 448;          // 56:  [t-1][p] = exp(-i*pi*t*p/32)
    float2* gbuf  = tw2 + 56;

    const int tid = threadIdx.x;
    const int g = tid >> 6;
    const int l = tid & 63;

    // ---- build tables (CTA-wide, once) ----
    for (int n = tid; n < 512; n += NTHREADS) {
        float s, c;
        float targ = (n < 256) ? (511.5f - 2.0f * n) * (1.0f / 2048.0f)
                               : (2.0f * n - 511.5f) * (1.0f / 2048.0f);
        sincospif(targ, &s, &c);
        wpair[n] = make_float2(c, s);

        sincospif(-(float)n * (1.0f / 1024.0f), &s, &c);
        apre[n] = make_float2(c, s);

        sincospif(-(4.0f * n + 1.0f) * (1.0f / 4096.0f), &s, &c);
        postt[n] = make_float2(SCALE * c, SCALE * s);
    }
    for (int i = tid; i < 448; i += NTHREADS) {
        int t = (i >> 6) + 1, ll = i & 63;
        float s, c;
        sincospif(-(float)(t * ll) * (1.0f / 256.0f), &s, &c);
        tw1[i] = make_float2(c, s);
    }
    if (tid < 56) {
        int t = (tid >> 3) + 1, p = tid & 7;
        float s, c;
        sincospif(-(float)(t * p) * (1.0f / 32.0f), &s, &c);
        tw2[tid] = make_float2(c, s);
    }
    __syncthreads();

    float2* bufA   = gbuf + g * GROUP_F2;
    float2* bufB   = bufA + BUF_F2;
    float*  stageF = (float*)bufA;       // reused after stage 2

    const int f = blockIdx.x * NGROUPS + g;
    const int b = blockIdx.y;
    const bool active = f < n_frames;

    const float* xb = x + (size_t)b * (size_t)T;
    const int start = f * 1024 - 1024;
    const bool interior = (f >= 1) && (start + 2048 <= T);

    #define GBAR() asm volatile("bar.sync %0, 64;" :: "r"(g + 1) : "memory")

    // ---- fold + pre-twiddle + stage 1 ----
    if (interior)
        fold_stage1_v2<false>(xb, start, T, l, wpair, apre, tw1, bufA);
    else
        fold_stage1_v2<true>(xb, start, T, l, wpair, apre, tw1, bufA);
    GBAR();

    // ---- stage 2 radix-8 ----
    {
        float2 a[8];
#pragma unroll
        for (int t = 0; t < 8; t++) a[t] = bufA[PHYS(l + 64 * t)];
        float2 A[8];
        dft8(a, A);
        int q = l & 7;
        int p = l >> 3;
#pragma unroll
        for (int t = 1; t < 8; t++) A[t] = cmulf(A[t], tw2[(t - 1) * 8 + p]);
        int j = 8 * l - 7 * q;
#pragma unroll
        for (int t = 0; t < 8; t++) bufB[PHYS(j + 8 * t)] = A[t];
    }
    GBAR();

    // ---- stage 3 radix-8 (no twiddle) + post-twiddle + de-interleave ----
    {
        float2 a[8];
#pragma unroll
        for (int t = 0; t < 8; t++) a[t] = bufB[PHYS(l + 64 * t)];
        float2 A[8];
        dft8(a, A);
#pragma unroll
        for (int t = 0; t < 8; t++) {
            int r = l + 64 * t;
            float2 pp = postt[r];
            stageF[XP(2 * r)]        = A[t].x * pp.x - A[t].y * pp.y;
            stageF[XP(1023 - 2 * r)] = -(A[t].x * pp.y + A[t].y * pp.x);
        }
    }
    GBAR();

    // ---- coalesced float4 store ----
    if (active) {
        float* ob = out + ((size_t)b * (size_t)n_frames + (size_t)f) * (size_t)NBINS;
#pragma unroll
        for (int m = 0; m < 4; m++) {
            int idx = 4 * (l + 64 * m);
            int p = XP(idx);
            float4 o = make_float4(stageF[p], stageF[p + 1], stageF[p + 2], stageF[p + 3]);
            *(float4*)(ob + idx) = o;
        }
    }
    #undef GBAR
}

extern "C" void kernel_launch(void* const* d_in, const int* in_sizes, int n_in,
                              void* d_out, int out_size) {
    const float* x = (const float*)d_in[0];
    float* out = (float*)d_out;

    const int B = 8;
    const int T = in_sizes[0] / B;        // 1<<20
    const int n_frames = T / 1024 + 1;    // 1025

    static bool attr_set = false;
    if (!attr_set) {
        cudaFuncSetAttribute(mdct_main, cudaFuncAttributeMaxDynamicSharedMemorySize,
                             SMEM_BYTES);
        attr_set = true;
    }

    dim3 grid((n_frames + NGROUPS - 1) / NGROUPS, B);
    mdct_main<<<grid, NTHREADS, SMEM_BYTES>>>(x, out, T, n_frames);
}

// round 7
// speedup vs baseline: 1.1001x; 1.1001x over previous
#include <cuda_runtime.h>
#include <math.h>

// Fast MDCT: B=8, T=2^20, F=2048, hop=1024, N=1024, n_frames=1025.
// fold 2048 real -> DCT-IV -> 512-pt complex FFT (3 radix-8 Stockham stages;
// stage 1 fused with fold, stage 3 fused with post-twiddle + paired gmem store).
// Persistent CTAs; per-CTA smem trig tables; XOR-swizzled conflict-free buffers.

#define NBINS 1024
#define SWZ(i) ((i) ^ (((i) >> 4) & 7) ^ ((((i) >> 6) & 1) << 3))   // bijection on [0,512)
#define BUF_F2 512
#define GROUP_F2 (2 * BUF_F2)          // bufA + bufB
#define NGROUPS 4
#define NTHREADS (64 * NGROUPS)
#define TBL_F2 (512 + 512 + 512 + 448 + 56)   // wpair, apre, post, tw1, tw2 = 2040
#define SMEM_F2 (TBL_F2 + NGROUPS * GROUP_F2)
#define SMEM_BYTES (SMEM_F2 * (int)sizeof(float2))
#define NUM_CTAS 608

#define PI_F 3.14159265358979323846f
#define SCALE 0.04419417382415922f    // sqrt(2/1024)

__device__ __forceinline__ float2 cmulf(float2 a, float2 b) {
    return make_float2(a.x * b.x - a.y * b.y, a.x * b.y + a.y * b.x);
}
__device__ __forceinline__ float2 caddf(float2 a, float2 b) { return make_float2(a.x + b.x, a.y + b.y); }
__device__ __forceinline__ float2 csubf(float2 a, float2 b) { return make_float2(a.x - b.x, a.y - b.y); }

// In-register 8-pt DFT (DIF), natural-order output.
__device__ __forceinline__ void dft8(const float2 a[8], float2 A[8]) {
    float2 e0 = caddf(a[0], a[4]), o0 = csubf(a[0], a[4]);
    float2 e1 = caddf(a[1], a[5]), o1 = csubf(a[1], a[5]);
    float2 e2 = caddf(a[2], a[6]), o2 = csubf(a[2], a[6]);
    float2 e3 = caddf(a[3], a[7]), o3 = csubf(a[3], a[7]);

    const float C = 0.70710678118654752f;
    float2 p1 = make_float2(C * (o1.x + o1.y), C * (o1.y - o1.x));
    float2 p2 = make_float2(o2.y, -o2.x);
    float2 p3 = make_float2(C * (o3.y - o3.x), -C * (o3.x + o3.y));

    float2 t0 = caddf(e0, e2), t1 = csubf(e0, e2);
    float2 t2 = caddf(e1, e3), t3 = csubf(e1, e3);
    A[0] = caddf(t0, t2);
    A[4] = csubf(t0, t2);
    A[2] = make_float2(t1.x + t3.y, t1.y - t3.x);
    A[6] = make_float2(t1.x - t3.y, t1.y + t3.x);

    float2 s0 = caddf(o0, p2), s1 = csubf(o0, p2);
    float2 s2 = caddf(p1, p3), s3 = csubf(p1, p3);
    A[1] = caddf(s0, s2);
    A[5] = csubf(s0, s2);
    A[3] = make_float2(s1.x + s3.y, s1.y - s3.x);
    A[7] = make_float2(s1.x - s3.y, s1.y + s3.x);
}

// Fold + pre-twiddle + stage-1 radix-8.  EDGE=true adds bounds checks.
template <bool EDGE>
__device__ __forceinline__ void fold_stage1(
    const float* __restrict__ xb, int start, int T, int l,
    const float2* __restrict__ wpair, const float2* __restrict__ apre,
    const float2* __restrict__ tw1, float2* __restrict__ bufA)
{
    const float* xf = xb + start;
    float2 v[8];
#pragma unroll
    for (int j = 0; j < 8; j++) {
        int n = l + 64 * j;
        int i0, i1, i2, i3;
        if (j < 4) { i0 = 1535 - 2 * n; i1 = 1536 + 2 * n; i2 = 511 - 2 * n;  i3 = 512 + 2 * n; }
        else       { i0 = 2 * n - 512;  i1 = 1535 - 2 * n; i2 = 512 + 2 * n;  i3 = 2559 - 2 * n; }

        float x0, x1, x2, x3;
        if (EDGE) {
            int g0 = start + i0, g1 = start + i1, g2 = start + i2, g3 = start + i3;
            x0 = ((unsigned)g0 < (unsigned)T) ? xb[g0] : 0.f;
            x1 = ((unsigned)g1 < (unsigned)T) ? xb[g1] : 0.f;
            x2 = ((unsigned)g2 < (unsigned)T) ? xb[g2] : 0.f;
            x3 = ((unsigned)g3 < (unsigned)T) ? xb[g3] : 0.f;
        } else {
            x0 = xf[i0]; x1 = xf[i1]; x2 = xf[i2]; x3 = xf[i3];
        }

        float2 w = wpair[n];
        float E, O;
        if (j < 4) { E = -(w.x * x0 + w.y * x1); O =  w.y * x2 - w.x * x3; }
        else       { E =   w.y * x0 - w.x * x1; O = -(w.x * x2 + w.y * x3); }
        float2 a = apre[n];
        v[j] = make_float2(E * a.x - O * a.y, E * a.y + O * a.x);
    }
    float2 A[8];
    dft8(v, A);
#pragma unroll
    for (int t = 1; t < 8; t++) A[t] = cmulf(A[t], tw1[(t - 1) * 64 + l]);
#pragma unroll
    for (int t = 0; t < 8; t++) bufA[SWZ(8 * l + t)] = A[t];
}

__global__ __launch_bounds__(NTHREADS, 4) void mdct_main(
    const float* __restrict__ x, float* __restrict__ out,
    int T, int n_frames, int total_frames)
{
    extern __shared__ float2 smem2[];
    float2* wpair = smem2;              // 512
    float2* apre  = wpair + 512;        // 512
    float2* postt = apre + 512;         // 512 (scale folded in)
    float2* tw1   = postt + 512;        // 448: [t-1][l] = exp(-i*pi*t*l/256)
    float2* tw2   = tw1 + 448;          // 56:  [t-1][p] = exp(-i*pi*t*p/32)
    float2* gbuf  = tw2 + 56;

    const int tid = threadIdx.x;
    const int g = tid >> 6;
    const int l = tid & 63;

    // ---- build tables once per CTA (fast MUFU trig; args <= 5.5 rad) ----
    for (int n = tid; n < 512; n += NTHREADS) {
        float s, c;
        float targ = (n < 256) ? (511.5f - 2.0f * n) : (2.0f * n - 511.5f);
        __sincosf(targ * (PI_F / 2048.0f), &s, &c);
        wpair[n] = make_float2(c, s);

        __sincosf(-(float)n * (PI_F / 1024.0f), &s, &c);
        apre[n] = make_float2(c, s);

        __sincosf(-(4.0f * n + 1.0f) * (PI_F / 4096.0f), &s, &c);
        postt[n] = make_float2(SCALE * c, SCALE * s);
    }
    for (int i = tid; i < 448; i += NTHREADS) {
        int t = (i >> 6) + 1, ll = i & 63;
        float s, c;
        __sincosf(-(float)(t * ll) * (PI_F / 256.0f), &s, &c);
        tw1[i] = make_float2(c, s);
    }
    if (tid < 56) {
        int t = (tid >> 3) + 1, p = tid & 7;
        float s, c;
        __sincosf(-(float)(t * p) * (PI_F / 32.0f), &s, &c);
        tw2[tid] = make_float2(c, s);
    }
    __syncthreads();

    float2* bufA = gbuf + g * GROUP_F2;
    float2* bufB = bufA + BUF_F2;

    // stage-3 row permutation: rows l and 63-l live at lanes l and l^16 (same warp)
    const int rbase = (l & 15) | (l & 32);
    const int ROW = (l & 16) ? (63 - rbase) : rbase;

    #define GBAR() asm volatile("bar.sync %0, 64;" :: "r"(g + 1) : "memory")

    // ---- persistent loop over frames ----
    for (int fi = blockIdx.x * NGROUPS + g; fi < total_frames;
         fi += (int)gridDim.x * NGROUPS) {

        const int b = fi / n_frames;
        const int f = fi - b * n_frames;
        const float* xb = x + (size_t)b * (size_t)T;
        const int start = f * 1024 - 1024;
        const bool interior = (start >= 0) && (start + 2048 <= T);

        // fold + pre-twiddle + stage 1
        if (interior)
            fold_stage1<false>(xb, start, T, l, wpair, apre, tw1, bufA);
        else
            fold_stage1<true>(xb, start, T, l, wpair, apre, tw1, bufA);
        GBAR();

        // stage 2 radix-8
        {
            float2 a[8];
#pragma unroll
            for (int t = 0; t < 8; t++) a[t] = bufA[SWZ(l + 64 * t)];
            float2 A[8];
            dft8(a, A);
            int q = l & 7;
            int p = l >> 3;
#pragma unroll
            for (int t = 1; t < 8; t++) A[t] = cmulf(A[t], tw2[(t - 1) * 8 + p]);
            int j = q + 64 * p;          // = 8l - 7q
#pragma unroll
            for (int t = 0; t < 8; t++) bufB[SWZ(j + 8 * t)] = A[t];
        }
        GBAR();

        // stage 3 radix-8 (no twiddle) + post-twiddle + shfl-paired store
        {
            float2 a[8];
#pragma unroll
            for (int t = 0; t < 8; t++) a[t] = bufB[SWZ(ROW + 64 * t)];
            float2 A[8];
            dft8(a, A);
            float2 P[8];
#pragma unroll
            for (int t = 0; t < 8; t++) P[t] = cmulf(A[t], postt[ROW + 64 * t]);

            float* ob = out + (size_t)fi * (size_t)NBINS;
#pragma unroll
            for (int t = 0; t < 8; t++) {
                // out[2r] = Re(P_l[t]);  out[2r+1] = -Im(P_{63-ROW}[7-t]) via lane^16
                float odd = __shfl_xor_sync(0xffffffffu, -P[7 - t].y, 16);
                int r = ROW + 64 * t;
                *(float2*)(ob + 2 * r) = make_float2(P[t].x, odd);
            }
        }
        GBAR();   // protect bufB before next iteration's stage 2
    }
    #undef GBAR
}

extern "C" void kernel_launch(void* const* d_in, const int* in_sizes, int n_in,
                              void* d_out, int out_size) {
    const float* x = (const float*)d_in[0];
    float* out = (float*)d_out;

    const int B = 8;
    const int T = in_sizes[0] / B;        // 1<<20
    const int n_frames = T / 1024 + 1;    // 1025
    const int total_frames = B * n_frames;

    static bool attr_set = false;
    if (!attr_set) {
        cudaFuncSetAttribute(mdct_main, cudaFuncAttributeMaxDynamicSharedMemorySize,
                             SMEM_BYTES);
        attr_set = true;
    }

    mdct_main<<<NUM_CTAS, NTHREADS, SMEM_BYTES>>>(x, out, T, n_frames, total_frames);
}

// round 8
// speedup vs baseline: 1.2076x; 1.0977x over previous
#include <cuda_runtime.h>
#include <math.h>

// Fast MDCT: B=8, T=2^20, F=2048, hop=1024, N=1024, n_frames=1025.
// fold 2048 real -> DCT-IV -> 512-pt complex FFT (3 radix-8 Stockham stages).
// Persistent CTAs; per-CTA smem trig tables; XOR-swizzled buffers;
// dense float2 fold loads with warp-shuffle even/odd redistribution.

#define NBINS 1024
#define SWZ(i) ((i) ^ (((i) >> 4) & 7) ^ ((((i) >> 6) & 1) << 3))
#define BUF_F2 512
#define GROUP_F2 (2 * BUF_F2)
#define NGROUPS 4
#define NTHREADS (64 * NGROUPS)
#define TBL_F2 (512 + 512 + 512 + 448 + 56)   // wpair, apre, post, tw1, tw2
#define SMEM_F2 (TBL_F2 + NGROUPS * GROUP_F2)
#define SMEM_BYTES (SMEM_F2 * (int)sizeof(float2))
#define NUM_CTAS 608

#define PI_F 3.14159265358979323846f
#define SCALE 0.04419417382415922f    // sqrt(2/1024)

__device__ __forceinline__ float2 cmulf(float2 a, float2 b) {
    return make_float2(a.x * b.x - a.y * b.y, a.x * b.y + a.y * b.x);
}
__device__ __forceinline__ float2 caddf(float2 a, float2 b) { return make_float2(a.x + b.x, a.y + b.y); }
__device__ __forceinline__ float2 csubf(float2 a, float2 b) { return make_float2(a.x - b.x, a.y - b.y); }

__device__ __forceinline__ void dft8(const float2 a[8], float2 A[8]) {
    float2 e0 = caddf(a[0], a[4]), o0 = csubf(a[0], a[4]);
    float2 e1 = caddf(a[1], a[5]), o1 = csubf(a[1], a[5]);
    float2 e2 = caddf(a[2], a[6]), o2 = csubf(a[2], a[6]);
    float2 e3 = caddf(a[3], a[7]), o3 = csubf(a[3], a[7]);

    const float C = 0.70710678118654752f;
    float2 p1 = make_float2(C * (o1.x + o1.y), C * (o1.y - o1.x));
    float2 p2 = make_float2(o2.y, -o2.x);
    float2 p3 = make_float2(C * (o3.y - o3.x), -C * (o3.x + o3.y));

    float2 t0 = caddf(e0, e2), t1 = csubf(e0, e2);
    float2 t2 = caddf(e1, e3), t3 = csubf(e1, e3);
    A[0] = caddf(t0, t2);
    A[4] = csubf(t0, t2);
    A[2] = make_float2(t1.x + t3.y, t1.y - t3.x);
    A[6] = make_float2(t1.x - t3.y, t1.y + t3.x);

    float2 s0 = caddf(o0, p2), s1 = csubf(o0, p2);
    float2 s2 = caddf(p1, p3), s3 = csubf(p1, p3);
    A[1] = caddf(s0, s2);
    A[5] = csubf(s0, s2);
    A[3] = make_float2(s1.x + s3.y, s1.y - s3.x);
    A[7] = make_float2(s1.x - s3.y, s1.y + s3.x);
}

// Branch-A/B fold arithmetic (n<256 / n>=256), shared by both load paths.
__device__ __forceinline__ float2 foldA(float x0, float x1, float x2, float x3,
                                        float2 w, float2 a) {
    float E = -(w.x * x0 + w.y * x1);
    float O =   w.y * x2 - w.x * x3;
    return make_float2(E * a.x - O * a.y, E * a.y + O * a.x);
}
__device__ __forceinline__ float2 foldB(float x0, float x1, float x2, float x3,
                                        float2 w, float2 a) {
    float E =   w.y * x0 - w.x * x1;
    float O = -(w.x * x2 + w.y * x3);
    return make_float2(E * a.x - O * a.y, E * a.y + O * a.x);
}

// Interior fold: dense float2 loads; odd elements swapped with lane^16.
// Butterfly index = ROW (paired with 63-ROW at lane^16, same warp).
__device__ __forceinline__ void fold_interior(
    const float* __restrict__ xf, int ROW,
    const float2* __restrict__ wpair, const float2* __restrict__ apre,
    float2 v[8])
{
#pragma unroll
    for (int s = 0; s < 4; s++) {
        const int na = ROW + 64 * s;          // branch A (n < 256)
        const int nb = ROW + 64 * (7 - s);    // branch B (n >= 256)

        // self loads: evens of each stream (all 8B-aligned, dense across warp)
        float2 fA1 = *(const float2*)(xf + 1536 + 2 * na);   // (y[1536+2na], y[1537+2na])
        float2 fA3 = *(const float2*)(xf + 512 + 2 * na);    // (y[512+2na],  y[513+2na])
        float2 fB0 = *(const float2*)(xf + 2 * nb - 512);    // (y[2nb-512],  y[2nb-511])
        float2 fB2 = *(const float2*)(xf + 512 + 2 * nb);    // (y[512+2nb],  y[513+2nb])

        // swap odd halves with partner lane (exact pairwise exchange)
        float oA0 = __shfl_xor_sync(0xffffffffu, fB2.y, 16);  // y[1535-2na]
        float oA2 = __shfl_xor_sync(0xffffffffu, fB0.y, 16);  // y[511-2na]
        float oB3 = __shfl_xor_sync(0xffffffffu, fA1.y, 16);  // y[2559-2nb]
        float oB1 = __shfl_xor_sync(0xffffffffu, fA3.y, 16);  // y[1535-2nb]

        v[s]     = foldA(oA0, fA1.x, oA2, fA3.x, wpair[na], apre[na]);
        v[7 - s] = foldB(fB0.x, oB1, fB2.x, oB3, wpair[nb], apre[nb]);
    }
}

// Edge fold: scalar guarded loads (frames touching the zero padding).
__device__ __forceinline__ void fold_edge(
    const float* __restrict__ xb, int start, int T, int ROW,
    const float2* __restrict__ wpair, const float2* __restrict__ apre,
    float2 v[8])
{
#pragma unroll
    for (int j = 0; j < 8; j++) {
        int n = ROW + 64 * j;
        int i0, i1, i2, i3;
        if (j < 4) { i0 = 1535 - 2 * n; i1 = 1536 + 2 * n; i2 = 511 - 2 * n;  i3 = 512 + 2 * n; }
        else       { i0 = 2 * n - 512;  i1 = 1535 - 2 * n; i2 = 512 + 2 * n;  i3 = 2559 - 2 * n; }

        int g0 = start + i0, g1 = start + i1, g2 = start + i2, g3 = start + i3;
        float x0 = ((unsigned)g0 < (unsigned)T) ? xb[g0] : 0.f;
        float x1 = ((unsigned)g1 < (unsigned)T) ? xb[g1] : 0.f;
        float x2 = ((unsigned)g2 < (unsigned)T) ? xb[g2] : 0.f;
        float x3 = ((unsigned)g3 < (unsigned)T) ? xb[g3] : 0.f;

        v[j] = (j < 4) ? foldA(x0, x1, x2, x3, wpair[n], apre[n])
                       : foldB(x0, x1, x2, x3, wpair[n], apre[n]);
    }
}

__global__ __launch_bounds__(NTHREADS, 4) void mdct_main(
    const float* __restrict__ x, float* __restrict__ out,
    int T, int n_frames, int total_frames)
{
    extern __shared__ float2 smem2[];
    float2* wpair = smem2;              // 512
    float2* apre  = wpair + 512;        // 512
    float2* postt = apre + 512;         // 512 (scale folded in)
    float2* tw1   = postt + 512;        // 448: [t-1][r] = exp(-i*pi*t*r/256)
    float2* tw2   = tw1 + 448;          // 56:  [t-1][p] = exp(-i*pi*t*p/32)
    float2* gbuf  = tw2 + 56;

    const int tid = threadIdx.x;
    const int g = tid >> 6;
    const int l = tid & 63;

    // ---- per-CTA tables (fast MUFU trig; args <= 5.5 rad) ----
    for (int n = tid; n < 512; n += NTHREADS) {
        float s, c;
        float targ = (n < 256) ? (511.5f - 2.0f * n) : (2.0f * n - 511.5f);
        __sincosf(targ * (PI_F / 2048.0f), &s, &c);
        wpair[n] = make_float2(c, s);

        __sincosf(-(float)n * (PI_F / 1024.0f), &s, &c);
        apre[n] = make_float2(c, s);

        __sincosf(-(4.0f * n + 1.0f) * (PI_F / 4096.0f), &s, &c);
        postt[n] = make_float2(SCALE * c, SCALE * s);
    }
    for (int i = tid; i < 448; i += NTHREADS) {
        int t = (i >> 6) + 1, ll = i & 63;
        float s, c;
        __sincosf(-(float)(t * ll) * (PI_F / 256.0f), &s, &c);
        tw1[i] = make_float2(c, s);
    }
    if (tid < 56) {
        int t = (tid >> 3) + 1, p = tid & 7;
        float s, c;
        __sincosf(-(float)(t * p) * (PI_F / 32.0f), &s, &c);
        tw2[tid] = make_float2(c, s);
    }
    __syncthreads();

    float2* bufA = gbuf + g * GROUP_F2;
    float2* bufB = bufA + BUF_F2;

    // ROW permutation: butterflies r and 63-r live at lanes l and l^16 (same warp)
    const int rbase = (l & 15) | (l & 32);
    const int ROW = (l & 16) ? (63 - rbase) : rbase;

    #define GBAR() asm volatile("bar.sync %0, 64;" :: "r"(g + 1) : "memory")

    for (int fi = blockIdx.x * NGROUPS + g; fi < total_frames;
         fi += (int)gridDim.x * NGROUPS) {

        const int b = fi / n_frames;
        const int f = fi - b * n_frames;
        const float* xb = x + (size_t)b * (size_t)T;
        const int start = f * 1024 - 1024;
        const bool interior = (start >= 0) && (start + 2048 <= T);

        // ---- fold + pre-twiddle + stage-1 radix-8 (butterfly ROW) ----
        {
            float2 v[8];
            if (interior) fold_interior(xb + start, ROW, wpair, apre, v);
            else          fold_edge(xb, start, T, ROW, wpair, apre, v);

            float2 A[8];
            dft8(v, A);
#pragma unroll
            for (int t = 1; t < 8; t++) A[t] = cmulf(A[t], tw1[(t - 1) * 64 + ROW]);
#pragma unroll
            for (int t = 0; t < 8; t++) bufA[SWZ(8 * ROW + t)] = A[t];
        }
        GBAR();

        // ---- stage 2 radix-8 (butterfly l) ----
        {
            float2 a[8];
#pragma unroll
            for (int t = 0; t < 8; t++) a[t] = bufA[SWZ(l + 64 * t)];
            float2 A[8];
            dft8(a, A);
            int q = l & 7;
            int p = l >> 3;
#pragma unroll
            for (int t = 1; t < 8; t++) A[t] = cmulf(A[t], tw2[(t - 1) * 8 + p]);
            int j = q + 64 * p;
#pragma unroll
            for (int t = 0; t < 8; t++) bufB[SWZ(j + 8 * t)] = A[t];
        }
        GBAR();

        // ---- stage 3 radix-8 + post-twiddle + shfl-paired store (butterfly ROW) ----
        {
            float2 a[8];
#pragma unroll
            for (int t = 0; t < 8; t++) a[t] = bufB[SWZ(ROW + 64 * t)];
            float2 A[8];
            dft8(a, A);
            float2 P[8];
#pragma unroll
            for (int t = 0; t < 8; t++) P[t] = cmulf(A[t], postt[ROW + 64 * t]);

            float* ob = out + (size_t)fi * (size_t)NBINS;
#pragma unroll
            for (int t = 0; t < 8; t++) {
                float odd = __shfl_xor_sync(0xffffffffu, -P[7 - t].y, 16);
                int r = ROW + 64 * t;
                *(float2*)(ob + 2 * r) = make_float2(P[t].x, odd);
            }
        }
        GBAR();   // protect buffers before next iteration
    }
    #undef GBAR
}

extern "C" void kernel_launch(void* const* d_in, const int* in_sizes, int n_in,
                              void* d_out, int out_size) {
    const float* x = (const float*)d_in[0];
    float* out = (float*)d_out;

    const int B = 8;
    const int T = in_sizes[0] / B;        // 1<<20
    const int n_frames = T / 1024 + 1;    // 1025
    const int total_frames = B * n_frames;

    static bool attr_set = false;
    if (!attr_set) {
        cudaFuncSetAttribute(mdct_main, cudaFuncAttributeMaxDynamicSharedMemorySize,
                             SMEM_BYTES);
        attr_set = true;
    }

    mdct_main<<<NUM_CTAS, NTHREADS, SMEM_BYTES>>>(x, out, T, n_frames, total_frames);
}